// round 11
// baseline (speedup 1.0000x reference)
#include <cuda_runtime.h>
#include <math.h>

// MultiConvPerm — all-bulk contiguous store variant.
// Each warp owns 4 consecutive output rows (16KB contiguous). It builds the
// complete 16KB image in shared memory (zeros + the two 29/28-float edge
// windows per row) and emits it as ONE cp.async.bulk 16KB burst.
//
// out[co,ci,:] (W=1024) is zero except:
//   out[x] = acc[28-x]    for x in [0,28]
//   out[x] = acc[1052-x]  for x in [996,1023]
// acc[t] = sum over static (wi,j) with t = p_wi + d_wi*j of coef[wi]*w_wi[row,j]
// coef   = softmax(alpha + gumbels)   (log_softmax shift cancels)

#define NW 12
#define NROWS 65536            // CO*CI = 256*256
#define WARPS_PER_BLOCK 4
#define ROWS_PER_WARP 4
#define IMG_FLOATS (ROWS_PER_WARP * 1024)          // 4096 floats = 16KB per warp
#define DYN_SMEM_BYTES (WARPS_PER_BLOCK * IMG_FLOATS * 4)  // 64KB

struct WPtrs {
    const float* w[NW];
};

// compile-time tap geometry (KD = product((3,5,7,9),(1,3,7)), S=57)
__device__ __forceinline__ void tap_params(int wi, int& k, int& d, int& p) {
    const int ks[NW] = {3,3,3, 5,5,5, 7,7,7, 9,9,9};
    const int ds[NW] = {1,3,7, 1,3,7, 1,3,7, 1,3,7};
    const int ps[NW] = {27,25,21, 26,22,14, 25,19,7, 24,16,0};
    k = ks[wi]; d = ds[wi]; p = ps[wi];
}

__device__ __forceinline__ unsigned int smem_u32(const void* p) {
    return (unsigned int)__cvta_generic_to_shared(p);
}

__global__ __launch_bounds__(WARPS_PER_BLOCK * 32)
void multiconv_bulk(WPtrs wp, const float* __restrict__ alpha,
                    const float* __restrict__ gumbels,
                    float* __restrict__ out) {
    extern __shared__ __align__(16) float dyn[];   // WARPS_PER_BLOCK * 4096 floats
    __shared__ float s_acc[WARPS_PER_BLOCK][ROWS_PER_WARP][64];
    __shared__ float s_coef[NW];

    const int tid = threadIdx.x;
    const int warp = tid >> 5;
    const int lane = tid & 31;

    const int row0 = (blockIdx.x * WARPS_PER_BLOCK + warp) * ROWS_PER_WARP;
    float* img = dyn + warp * IMG_FLOATS;

    // ---- coef = softmax(alpha + gumbels), threads 0..11 redundantly --------
    if (tid < NW) {
        float v[NW];
        float m = -1e30f;
        #pragma unroll
        for (int i = 0; i < NW; i++) {
            v[i] = alpha[i] + gumbels[i];
            m = fmaxf(m, v[i]);
        }
        float s = 0.0f;
        #pragma unroll
        for (int i = 0; i < NW; i++) {
            v[i] = __expf(v[i] - m);
            s += v[i];
        }
        s_coef[tid] = v[tid] * __fdividef(1.0f, s);
    }

    // ---- zero the 16KB warp image (32 STS.128 per lane) --------------------
    {
        const float4 z = make_float4(0.f, 0.f, 0.f, 0.f);
        float4* img4 = reinterpret_cast<float4*>(img);
        #pragma unroll
        for (int i = 0; i < IMG_FLOATS / 4 / 32; i++) {
            img4[i * 32 + lane] = z;
        }
    }
    __syncthreads();   // s_coef ready (also covers image zeroing)

    // ---- per-lane accumulators over static taps ----------------------------
    // lane owns t0 = lane and t1 = lane+32 (valid while t1 <= 56)
    float f0[ROWS_PER_WARP], f1[ROWS_PER_WARP];
    #pragma unroll
    for (int r = 0; r < ROWS_PER_WARP; r++) { f0[r] = 0.0f; f1[r] = 0.0f; }

    const bool hasHi = (lane < 25);

    #pragma unroll
    for (int wi = 0; wi < NW; wi++) {
        int k, d, p;
        tap_params(wi, k, d, p);

        const int u0 = lane - p;
        const int u1 = lane + 32 - p;
        const bool v0 = (u0 >= 0) && (u0 % d == 0) && (u0 / d < k);
        const bool v1 = hasHi && (u1 >= 0) && (u1 % d == 0) && (u1 / d < k);
        const int j0 = u0 / d;
        const int j1 = u1 / d;

        const float c = s_coef[wi];
        const float* base = wp.w[wi] + (size_t)row0 * k;
        #pragma unroll
        for (int r = 0; r < ROWS_PER_WARP; r++) {
            if (v0) f0[r] += c * base[r * k + j0];
            if (v1) f1[r] += c * base[r * k + j1];
        }
    }

    #pragma unroll
    for (int r = 0; r < ROWS_PER_WARP; r++) {
        s_acc[warp][r][lane] = f0[r];
        if (hasHi) s_acc[warp][r][lane + 32] = f1[r];
    }
    __syncwarp();

    // ---- write edge windows into the image ---------------------------------
    // head of row r: x in [0,32): val = (x<=28) ? acc[28-x] : 0  -> lanes 0..7
    // tail of row r: x in [992,1024): val = (x>=996) ? acc[1052-x] : 0 -> lanes 8..15
    // (image already zeroed; only touch the nonzero 8-float4 windows)
    #pragma unroll
    for (int r = 0; r < ROWS_PER_WARP; r++) {
        const float* A = s_acc[warp][r];
        float* rowp = img + r * 1024;
        if (lane < 8) {
            const int x = lane * 4;
            float4 v;
            v.x = (x + 0 < 29) ? A[28 - (x + 0)] : 0.0f;
            v.y = (x + 1 < 29) ? A[28 - (x + 1)] : 0.0f;
            v.z = (x + 2 < 29) ? A[28 - (x + 2)] : 0.0f;
            v.w = (x + 3 < 29) ? A[28 - (x + 3)] : 0.0f;
            *reinterpret_cast<float4*>(rowp + x) = v;
        } else if (lane < 16) {
            const int x = 992 + (lane - 8) * 4;
            float4 v;
            v.x = (x + 0 >= 996) ? A[1052 - (x + 0)] : 0.0f;
            v.y = (x + 1 >= 996) ? A[1052 - (x + 1)] : 0.0f;
            v.z = (x + 2 >= 996) ? A[1052 - (x + 2)] : 0.0f;
            v.w = (x + 3 >= 996) ? A[1052 - (x + 3)] : 0.0f;
            *reinterpret_cast<float4*>(rowp + x) = v;
        }
    }
    __syncwarp();

    // ---- one contiguous 16KB bulk store per warp ---------------------------
    if (lane == 0) {
        asm volatile("fence.proxy.async.shared::cta;" ::: "memory");
        float* dst = out + (size_t)row0 * 1024;
        asm volatile(
            "cp.async.bulk.global.shared::cta.bulk_group [%0], [%1], %2;"
            :: "l"(dst), "r"(smem_u32(img)), "r"(IMG_FLOATS * 4) : "memory");
        asm volatile("cp.async.bulk.commit_group;" ::: "memory");
        asm volatile("cp.async.bulk.wait_group 0;" ::: "memory");
    }
}

// ---------------- generic-W fallback (proven R6-style path) -----------------
__global__ __launch_bounds__(256)
void multiconv_generic(WPtrs wp, const float* __restrict__ alpha,
                       const float* __restrict__ gumbels,
                       float* __restrict__ out, int W) {
    __shared__ float s_acc[8][ROWS_PER_WARP][64];
    __shared__ float s_coef[NW];

    const int tid = threadIdx.x;
    const int warp = tid >> 5;
    const int lane = tid & 31;
    const int row0 = (blockIdx.x * 8 + warp) * ROWS_PER_WARP;

    if (tid < NW) {
        float v[NW];
        float m = -1e30f;
        #pragma unroll
        for (int i = 0; i < NW; i++) {
            v[i] = alpha[i] + gumbels[i];
            m = fmaxf(m, v[i]);
        }
        float s = 0.0f;
        #pragma unroll
        for (int i = 0; i < NW; i++) { v[i] = __expf(v[i] - m); s += v[i]; }
        s_coef[tid] = v[tid] * __fdividef(1.0f, s);
    }
    __syncthreads();

    float f0[ROWS_PER_WARP], f1[ROWS_PER_WARP];
    #pragma unroll
    for (int r = 0; r < ROWS_PER_WARP; r++) { f0[r] = 0.0f; f1[r] = 0.0f; }

    const bool hasHi = (lane < 25);
    #pragma unroll
    for (int wi = 0; wi < NW; wi++) {
        int k, d, p;
        tap_params(wi, k, d, p);
        const int u0 = lane - p, u1 = lane + 32 - p;
        const bool v0 = (u0 >= 0) && (u0 % d == 0) && (u0 / d < k);
        const bool v1 = hasHi && (u1 >= 0) && (u1 % d == 0) && (u1 / d < k);
        const int j0 = u0 / d, j1 = u1 / d;
        const float c = s_coef[wi];
        const float* base = wp.w[wi] + (size_t)row0 * k;
        #pragma unroll
        for (int r = 0; r < ROWS_PER_WARP; r++) {
            if (v0) f0[r] += c * base[r * k + j0];
            if (v1) f1[r] += c * base[r * k + j1];
        }
    }
    #pragma unroll
    for (int r = 0; r < ROWS_PER_WARP; r++) {
        s_acc[warp][r][lane] = f0[r];
        if (hasHi) s_acc[warp][r][lane + 32] = f1[r];
    }
    __syncwarp();

    const int lo = 29, hi = W - 28;
    #pragma unroll
    for (int r = 0; r < ROWS_PER_WARP; r++) {
        const float* A = s_acc[warp][r];
        float* orow = out + (size_t)(row0 + r) * (size_t)W;
        for (int x0 = lane * 4; x0 < W; x0 += 128) {
            float4 v;
            #pragma unroll
            for (int q = 0; q < 4; q++) {
                const int x = x0 + q;
                float f = 0.0f;
                if (x < lo) f = A[28 - x];
                else if (x >= hi) f = A[W + 28 - x];
                (&v.x)[q] = f;
            }
            *reinterpret_cast<float4*>(orow + x0) = v;
        }
    }
}

extern "C" void kernel_launch(void* const* d_in, const int* in_sizes, int n_in,
                              void* d_out, int out_size) {
    WPtrs wp;
    for (int i = 0; i < NW; i++) wp.w[i] = (const float*)d_in[i];
    const float* alpha = (const float*)d_in[12];
    const float* gumbels = (const float*)d_in[13];
    float* out = (float*)d_out;

    const int W = out_size / NROWS;  // spatial size (1024)

    if (W == 1024) {
        cudaFuncSetAttribute(multiconv_bulk,
                             cudaFuncAttributeMaxDynamicSharedMemorySize,
                             DYN_SMEM_BYTES);
        const int rows_per_block = WARPS_PER_BLOCK * ROWS_PER_WARP;  // 16
        const int grid = NROWS / rows_per_block;                     // 4096
        multiconv_bulk<<<grid, WARPS_PER_BLOCK * 32, DYN_SMEM_BYTES>>>(
            wp, alpha, gumbels, out);
    } else {
        const int rows_per_block = 8 * ROWS_PER_WARP;
        const int grid = (NROWS + rows_per_block - 1) / rows_per_block;
        multiconv_generic<<<grid, 256>>>(wp, alpha, gumbels, out, W);
    }
}

// round 12
// speedup vs baseline: 1.4860x; 1.4860x over previous
#include <cuda_runtime.h>
#include <math.h>

// MultiConvPerm, fused single kernel, hybrid store path (R9 config, slim edges):
//   - floats [32,992) of each 1024-row are zeros -> one cp.async.bulk (3840B/row)
//     from a shared 3840B zero buffer (same source for every row)
//   - floats [0,32) and [992,1024) -> ONE STG.128 per row, 16 active lanes
//
// out[co,ci,:] (W=1024) is zero except:
//   out[x] = acc[28-x]    for x in [0,28]
//   out[x] = acc[1052-x]  for x in [996,1023]
// acc[t] = sum over static (wi,j) with t = p_wi + d_wi*j of coef[wi]*w_wi[row,j]
// coef   = softmax(alpha + gumbels)   (log_softmax shift cancels)

#define NW 12
#define NROWS 65536            // CO*CI = 256*256
#define WARPS_PER_BLOCK 8
#define ROWS_PER_WARP 4
#define ZERO_FLOATS 960        // floats [32,992) per row, 3840 bytes

struct WPtrs {
    const float* w[NW];
};

// compile-time tap geometry (KD = product((3,5,7,9),(1,3,7)), S=57)
__device__ __forceinline__ void tap_params(int wi, int& k, int& d, int& p) {
    const int ks[NW] = {3,3,3, 5,5,5, 7,7,7, 9,9,9};
    const int ds[NW] = {1,3,7, 1,3,7, 1,3,7, 1,3,7};
    const int ps[NW] = {27,25,21, 26,22,14, 25,19,7, 24,16,0};
    k = ks[wi]; d = ds[wi]; p = ps[wi];
}

__device__ __forceinline__ unsigned int smem_u32(const void* p) {
    return (unsigned int)__cvta_generic_to_shared(p);
}

template<bool FAST1024>
__global__ __launch_bounds__(WARPS_PER_BLOCK * 32)
void multiconv_kernel(WPtrs wp, const float* __restrict__ alpha,
                      const float* __restrict__ gumbels,
                      float* __restrict__ out, int W) {
    __shared__ __align__(16) float s_zero[ZERO_FLOATS];
    __shared__ float s_acc[WARPS_PER_BLOCK][ROWS_PER_WARP][64];

    const int tid = threadIdx.x;
    const int warp = tid >> 5;
    const int lane = tid & 31;

    const int row0 = (blockIdx.x * WARPS_PER_BLOCK + warp) * ROWS_PER_WARP;

    // ---- init shared zero buffer (once per block) --------------------------
    if (FAST1024) {
        if (tid < ZERO_FLOATS / 4) {
            reinterpret_cast<float4*>(s_zero)[tid] = make_float4(0.f, 0.f, 0.f, 0.f);
        }
        // make generic-proxy smem writes visible to the async (bulk-copy) proxy
        asm volatile("fence.proxy.async.shared::cta;" ::: "memory");
        __syncthreads();

        // ---- phase A: one 3840B bulk zero-store per row, deep async queue --
        if (lane == 0) {
            const unsigned int src = smem_u32(s_zero);
            #pragma unroll
            for (int r = 0; r < ROWS_PER_WARP; r++) {
                float* dst = out + (size_t)(row0 + r) * 1024 + 32;
                asm volatile(
                    "cp.async.bulk.global.shared::cta.bulk_group [%0], [%1], %2;"
                    :: "l"(dst), "r"(src), "r"(ZERO_FLOATS * 4) : "memory");
            }
            asm volatile("cp.async.bulk.commit_group;" ::: "memory");
        }
    }

    // ---- coef = softmax(alpha + gumbels), fast-math, hides under stores ----
    float coef[NW];
    {
        float m = -1e30f;
        #pragma unroll
        for (int i = 0; i < NW; i++) {
            coef[i] = alpha[i] + gumbels[i];
            m = fmaxf(m, coef[i]);
        }
        float s = 0.0f;
        #pragma unroll
        for (int i = 0; i < NW; i++) {
            coef[i] = __expf(coef[i] - m);
            s += coef[i];
        }
        const float inv = __fdividef(1.0f, s);
        #pragma unroll
        for (int i = 0; i < NW; i++) coef[i] *= inv;
    }

    // ---- phase B: per-lane accumulators over static taps -------------------
    // lane owns t0 = lane and t1 = lane+32 (valid while t1 <= 56)
    float f0[ROWS_PER_WARP], f1[ROWS_PER_WARP];
    #pragma unroll
    for (int r = 0; r < ROWS_PER_WARP; r++) { f0[r] = 0.0f; f1[r] = 0.0f; }

    const bool hasHi = (lane < 25);

    #pragma unroll
    for (int wi = 0; wi < NW; wi++) {
        int k, d, p;
        tap_params(wi, k, d, p);

        const int u0 = lane - p;
        const int u1 = lane + 32 - p;
        const bool v0 = (u0 >= 0) && (u0 % d == 0) && (u0 / d < k);
        const bool v1 = hasHi && (u1 >= 0) && (u1 % d == 0) && (u1 / d < k);
        const int j0 = u0 / d;
        const int j1 = u1 / d;

        const float c = coef[wi];
        const float* base = wp.w[wi] + (size_t)row0 * k;
        #pragma unroll
        for (int r = 0; r < ROWS_PER_WARP; r++) {
            if (v0) f0[r] += c * base[r * k + j0];
            if (v1) f1[r] += c * base[r * k + j1];
        }
    }

    #pragma unroll
    for (int r = 0; r < ROWS_PER_WARP; r++) {
        s_acc[warp][r][lane] = f0[r];
        if (hasHi) s_acc[warp][r][lane + 32] = f1[r];
    }
    __syncwarp();

    // ---- phase C: edge stores — ONE STG.128 per row, 16 active lanes -------
    if (FAST1024) {
        #pragma unroll
        for (int r = 0; r < ROWS_PER_WARP; r++) {
            const float* A = s_acc[warp][r];
            float* orow = out + (size_t)(row0 + r) * 1024;
            if (lane < 16) {
                // lanes 0..7: head floats [0,32); lanes 8..15: tail [992,1024)
                const int x = (lane < 8) ? (lane * 4) : (992 + (lane - 8) * 4);
                float4 v;
                #pragma unroll
                for (int q = 0; q < 4; q++) {
                    const int xx = x + q;
                    float f = 0.0f;
                    if (xx < 32) {
                        if (xx < 29) f = A[28 - xx];
                    } else {
                        if (xx >= 996) f = A[1052 - xx];
                    }
                    (&v.x)[q] = f;
                }
                *reinterpret_cast<float4*>(orow + x) = v;
            }
        }
        // drain this warp's bulk-store group before block exit
        if (lane == 0) {
            asm volatile("cp.async.bulk.wait_group 0;" ::: "memory");
        }
    } else {
        const int lo = 29, hi = W - 28;
        #pragma unroll
        for (int r = 0; r < ROWS_PER_WARP; r++) {
            const float* A = s_acc[warp][r];
            float* orow = out + (size_t)(row0 + r) * (size_t)W;
            for (int x0 = lane * 4; x0 < W; x0 += 128) {
                float4 v;
                #pragma unroll
                for (int q = 0; q < 4; q++) {
                    const int x = x0 + q;
                    float f = 0.0f;
                    if (x < lo) f = A[28 - x];
                    else if (x >= hi) f = A[W + 28 - x];
                    (&v.x)[q] = f;
                }
                *reinterpret_cast<float4*>(orow + x0) = v;
            }
        }
    }
}

extern "C" void kernel_launch(void* const* d_in, const int* in_sizes, int n_in,
                              void* d_out, int out_size) {
    WPtrs wp;
    for (int i = 0; i < NW; i++) wp.w[i] = (const float*)d_in[i];
    const float* alpha = (const float*)d_in[12];
    const float* gumbels = (const float*)d_in[13];
    float* out = (float*)d_out;

    const int W = out_size / NROWS;  // spatial size (1024)
    const int rows_per_block = WARPS_PER_BLOCK * ROWS_PER_WARP;
    const int grid = (NROWS + rows_per_block - 1) / rows_per_block;

    if (W == 1024) {
        multiconv_kernel<true><<<grid, WARPS_PER_BLOCK * 32>>>(wp, alpha, gumbels, out, W);
    } else {
        multiconv_kernel<false><<<grid, WARPS_PER_BLOCK * 32>>>(wp, alpha, gumbels, out, W);
    }
}